// round 8
// baseline (speedup 1.0000x reference)
#include <cuda_runtime.h>
#include <cuda_bf16.h>
#include <cstdint>
#include <cstddef>

#define B_    128
#define T_    512
#define IN_   64
#define H_    1024
#define OUT_  64

#define NCTA   128           // 4 b-groups x 32 h-groups
#define KP_REC 512           // recurrent k-pairs
#define KP_IN  32            // input k-pairs
#define KP_TOT (KP_REC + KP_IN)

typedef unsigned long long u64;

// ---------------- static device scratch --------------------------------------
__device__ u64   g_frP[2][KP_REC][B_];     // fr state pair-packed [kp][b], ping-pong
__device__ u64   g_xP[T_][KP_IN][B_];      // input-proj operand pair-packed
__device__ u64   g_W[KP_TOT][H_];          // W_rec/W_in pair-packed, [kp][h] (4.46 MB)
__device__ u64   g_WoutP[KP_REC * OUT_];   // W_out pair-packed [kp][o]
__device__ unsigned g_arrive[4];           // per-b-group arrival counters
__device__ unsigned g_epoch[4];            // per-b-group released epochs

// ---------------- helpers -----------------------------------------------------
static __device__ __forceinline__ u64 pack2(float x, float y) {
    u64 r; asm("mov.b64 %0, {%1,%2};" : "=l"(r) : "f"(x), "f"(y)); return r;
}
static __device__ __forceinline__ float2 unpack2(u64 v) {
    float2 r; asm("mov.b64 {%0,%1}, %2;" : "=f"(r.x), "=f"(r.y) : "l"(v)); return r;
}
// packed fp32x2 FMA (Blackwell FFMA2): acc += a*b on both lanes
static __device__ __forceinline__ void fma2(u64& acc, u64 a, u64 b) {
    asm("fma.rn.f32x2 %0, %1, %2, %0;" : "+l"(acc) : "l"(a), "l"(b));
}
static __device__ __forceinline__ unsigned ld_acq(const unsigned* p) {
    unsigned v;
    asm volatile("ld.acquire.gpu.global.u32 %0, [%1];" : "=r"(v) : "l"(p));
    return v;
}
static __device__ __forceinline__ void st_rel(unsigned* p, unsigned v) {
    asm volatile("st.release.gpu.global.u32 [%0], %1;" :: "l"(p), "r"(v) : "memory");
}

// ============================================================================
// Prep: pack input-projection operand [T][KP_IN][B]
// ============================================================================
__global__ void k_prep_x(const float* __restrict__ inp) {
    int i = blockIdx.x * 256 + threadIdx.x;            // T_*KP_IN*B_ = 2097152
    if (i >= T_ * KP_IN * B_) return;
    int b  = i & 127;
    int kq = (i >> 7) & 31;
    int t  = i >> 12;
    const float* s = inp + ((size_t)b * T_ + t) * IN_ + 2 * kq;
    g_xP[t][kq][b] = pack2(s[0], s[1]);
}

// Prep: W_rec / W_in -> g_W[kp][h] pair-packed transpose
__global__ void k_prep_w(const float* __restrict__ Wrecw,
                         const float* __restrict__ Winw) {
    int i = blockIdx.x * 256 + threadIdx.x;            // 524288 threads
    {   // rec: kp fast for coalesced source reads
        int kp = i & 511, h = i >> 9;                  // h < 1024
        const float* s = Wrecw + (size_t)h * H_ + 2 * kp;
        g_W[kp][h] = pack2(s[0], s[1]);
    }
    if (i < KP_IN * H_) {                              // 32768
        int kq = i & 31, h = i >> 5;
        const float* s = Winw + (size_t)h * IN_ + 2 * kq;
        g_W[KP_REC + kq][h] = pack2(s[0], s[1]);
    }
}

// Prep: fr0 pack, W_out pair-pack, barrier reset
__global__ void k_prep_misc(const float* __restrict__ fr0,
                            const float* __restrict__ Woutw) {
    int i = blockIdx.x * 256 + threadIdx.x;            // 65536 threads
    {   // fr0 -> g_frP[0]
        int b = i & 127, hp = i >> 7;                  // hp < 512
        const float* s = fr0 + (size_t)b * H_ + 2 * hp;
        g_frP[0][hp][b] = pack2(s[0], s[1]);
    }
    if (i < KP_REC * OUT_) {                           // 32768
        int kp = i & 511, o = i >> 9;
        const float* s = Woutw + (size_t)o * H_ + 2 * kp;
        g_WoutP[(size_t)kp * OUT_ + o] = pack2(s[0], s[1]);
    }
    if (i < 4) { g_arrive[i] = 0u; g_epoch[i] = 0u; }
}

// ============================================================================
// Persistent recurrent loop: CTA = (bg 0..3) x (hg 0..31), 256 threads.
// Compute role: thread = (bp 0..15 [2 b], hp 0..3 [8 h], ks 0..3 [136 kp]).
//   Per k-pair: 1x16B fr (ldcg) + 4x16B W (ldg, L2/L1) -> 16 FFMA2.
// Epilogue role: thread = (eb 0..31, ehq 0..7 [4 h]); fr kept in registers.
// ============================================================================
__global__ void __launch_bounds__(256, 1)
k_rnn(const float* __restrict__ noise,
      const float* __restrict__ Winb,  const float* __restrict__ Wrecb,
      const float* __restrict__ fr0,
      float* __restrict__ out_rates)
{
    __shared__ float sRed[4][32][33];     // [ks][b][h] partial sums (16.9 KB)
    __shared__ float sB[32];

    const int tid = threadIdx.x;
    const int bg  = blockIdx.x & 3;
    const int hg  = blockIdx.x >> 2;
    const int b0  = bg * 32;
    const int h0  = hg * 32;

    if (tid < 32) sB[tid] = Winb[h0 + tid] + Wrecb[h0 + tid];

    // ---- epilogue role: thread owns (eb, 4 h), fr kept in registers ---------
    const int eb  = tid >> 3;            // 0..31
    const int ehq = tid & 7;             // h = h0 + ehq*4 .. +3
    const int ebg = b0 + eb;
    const int ehg = h0 + ehq * 4;
    float frloc[4];
    {
        float4 f = *reinterpret_cast<const float4*>(fr0 + (size_t)ebg * H_ + ehg);
        frloc[0] = f.x; frloc[1] = f.y; frloc[2] = f.z; frloc[3] = f.w;
    }

    // ---- compute role ---------------------------------------------------------
    const int bp = tid & 15;             // b-pair (b = b0 + 2bp, +1)
    const int hp = (tid >> 4) & 3;       // h-octet (h = h0 + hp*8 .. +7)
    const int ks = tid >> 6;             // k-slice (128 rec kp + 8 input kp)
    const u64* wrec0 = &g_W[ks * 128][h0 + hp * 8];
    const u64* wx0   = &g_W[KP_REC + ks * 8][h0 + hp * 8];
    __syncthreads();

    for (int t = 0; t < T_; ++t) {
        const u64* cur = &g_frP[t & 1][0][0];
        u64*       nxt = &g_frP[(t + 1) & 1][0][0];

        u64 acc[16];
        #pragma unroll
        for (int j = 0; j < 16; ++j) acc[j] = 0ull;

        // recurrent part: 128 k-pairs
        {
            const u64* frp = cur + (size_t)(ks * 128) * B_ + (b0 + 2 * bp);
            const u64* wp  = wrec0;
            #pragma unroll 8
            for (int i = 0; i < 128; ++i) {
                ulonglong2 f = __ldcg(reinterpret_cast<const ulonglong2*>(frp));
                frp += B_;
                const ulonglong2* w2 = reinterpret_cast<const ulonglong2*>(wp);
                wp += H_;
                ulonglong2 wa = w2[0], wb = w2[1], wc = w2[2], wd = w2[3];
                fma2(acc[0], f.x, wa.x);  fma2(acc[1], f.x, wa.y);
                fma2(acc[2], f.x, wb.x);  fma2(acc[3], f.x, wb.y);
                fma2(acc[4], f.x, wc.x);  fma2(acc[5], f.x, wc.y);
                fma2(acc[6], f.x, wd.x);  fma2(acc[7], f.x, wd.y);
                fma2(acc[8],  f.y, wa.x); fma2(acc[9],  f.y, wa.y);
                fma2(acc[10], f.y, wb.x); fma2(acc[11], f.y, wb.y);
                fma2(acc[12], f.y, wc.x); fma2(acc[13], f.y, wc.y);
                fma2(acc[14], f.y, wd.x); fma2(acc[15], f.y, wd.y);
            }
        }
        // input-projection part: 8 k-pairs
        {
            const u64* xp = &g_xP[t][ks * 8][0] + (b0 + 2 * bp);
            const u64* wp = wx0;
            #pragma unroll
            for (int j = 0; j < 8; ++j) {
                ulonglong2 f = *reinterpret_cast<const ulonglong2*>(xp);
                xp += B_;
                const ulonglong2* w2 = reinterpret_cast<const ulonglong2*>(wp);
                wp += H_;
                ulonglong2 wa = w2[0], wb = w2[1], wc = w2[2], wd = w2[3];
                fma2(acc[0], f.x, wa.x);  fma2(acc[1], f.x, wa.y);
                fma2(acc[2], f.x, wb.x);  fma2(acc[3], f.x, wb.y);
                fma2(acc[4], f.x, wc.x);  fma2(acc[5], f.x, wc.y);
                fma2(acc[6], f.x, wd.x);  fma2(acc[7], f.x, wd.y);
                fma2(acc[8],  f.y, wa.x); fma2(acc[9],  f.y, wa.y);
                fma2(acc[10], f.y, wb.x); fma2(acc[11], f.y, wb.y);
                fma2(acc[12], f.y, wc.x); fma2(acc[13], f.y, wc.y);
                fma2(acc[14], f.y, wd.x); fma2(acc[15], f.y, wd.y);
            }
        }
        // pair-sum -> reduction smem
        #pragma unroll
        for (int e = 0; e < 2; ++e)
            #pragma unroll
            for (int j = 0; j < 8; ++j) {
                float2 v = unpack2(acc[e * 8 + j]);
                sRed[ks][2 * bp + e][hp * 8 + j] = v.x + v.y;
            }
        __syncthreads();

        // ---- epilogue: 4-way k reduce, bias+noise, tanh, leaky update --------
        {
            float4 n = *reinterpret_cast<const float4*>(
                noise + ((size_t)t * B_ + ebg) * H_ + ehg);
            float nn[4] = {n.x, n.y, n.z, n.w};
            #pragma unroll
            for (int j = 0; j < 4; ++j) {
                int h = ehq * 4 + j;
                float s = sRed[0][eb][h] + sRed[1][eb][h]
                        + sRed[2][eb][h] + sRed[3][eb][h];
                frloc[j] = 0.9f * frloc[j] + 0.1f * tanhf(s + sB[h] + nn[j]);
            }
            const size_t kp0 = (size_t)(ehg >> 1);
            __stcg(nxt + kp0 * B_ + ebg,       pack2(frloc[0], frloc[1]));
            __stcg(nxt + (kp0 + 1) * B_ + ebg, pack2(frloc[2], frloc[3]));
            *reinterpret_cast<float4*>(
                out_rates + ((size_t)ebg * T_ + t) * H_ + ehg) =
                make_float4(frloc[0], frloc[1], frloc[2], frloc[3]);
        }

        // ---- per-b-group grid barrier (32 CTAs) ------------------------------
        if (t < T_ - 1) {
            __threadfence();
            __syncthreads();
            if (tid == 0) {
                unsigned old = atomicAdd(&g_arrive[bg], 1u);
                if (old == 32u * (unsigned)(t + 1) - 1u) {
                    st_rel(&g_epoch[bg], (unsigned)(t + 1));
                } else {
                    while (ld_acq(&g_epoch[bg]) < (unsigned)(t + 1)) {}
                }
            }
            __syncthreads();
        }
    }
}

// ============================================================================
// preds: sigmoid(fr_{t-1} @ Wout^T + b). Tiled GEMM: 64 rows x 64 outs/block.
// (verified in R6/R7 — unchanged)
// ============================================================================
#define PR_CH    32                    // k-pairs per chunk
#define PR_PITCH 66                    // u64 pitch

__global__ void __launch_bounds__(256)
k_preds(const float* __restrict__ fr0,
        const float* __restrict__ Woutb,
        const float* __restrict__ rates,
        float* __restrict__ preds)
{
    __shared__ __align__(16) u64 sFr[PR_CH][PR_PITCH];
    __shared__ __align__(16) u64 sWo[PR_CH][PR_PITCH];

    const int tid  = threadIdx.x;
    const int rx   = tid >> 4;
    const int ox   = tid & 15;
    const int row0 = blockIdx.x * 64;

    u64 acc[16];
    #pragma unroll
    for (int j = 0; j < 16; ++j) acc[j] = 0ull;

    for (int c = 0; c < KP_REC / PR_CH; ++c) {
        #pragma unroll
        for (int it = 0; it < 4; ++it) {
            int i  = tid + it * 256;
            int f4 = i & 15, r = i >> 4;
            int row = row0 + r;
            int bb = row >> 9, tt = row & (T_ - 1);
            const float4* src = (tt == 0)
                ? reinterpret_cast<const float4*>(fr0 + (size_t)bb * H_)
                : reinterpret_cast<const float4*>(
                      rates + ((size_t)bb * T_ + (tt - 1)) * H_);
            float4 v = src[c * 16 + f4];
            sFr[f4 * 2][r]     = pack2(v.x, v.y);
            sFr[f4 * 2 + 1][r] = pack2(v.z, v.w);
        }
        #pragma unroll
        for (int it = 0; it < 4; ++it) {
            int i   = tid + it * 256;
            int u2  = i & 31, kpl = i >> 5;
            ulonglong2 v = *reinterpret_cast<const ulonglong2*>(
                &g_WoutP[(size_t)(c * PR_CH + kpl) * OUT_ + u2 * 2]);
            *reinterpret_cast<ulonglong2*>(&sWo[kpl][u2 * 2]) = v;
        }
        __syncthreads();

        #pragma unroll 4
        for (int kpl = 0; kpl < PR_CH; ++kpl) {
            ulonglong2 f01 = *reinterpret_cast<const ulonglong2*>(&sFr[kpl][rx * 4]);
            ulonglong2 f23 = *reinterpret_cast<const ulonglong2*>(&sFr[kpl][rx * 4 + 2]);
            ulonglong2 w01 = *reinterpret_cast<const ulonglong2*>(&sWo[kpl][ox * 4]);
            ulonglong2 w23 = *reinterpret_cast<const ulonglong2*>(&sWo[kpl][ox * 4 + 2]);
            u64 fr2[4] = {f01.x, f01.y, f23.x, f23.y};
            u64 wo2[4] = {w01.x, w01.y, w23.x, w23.y};
            #pragma unroll
            for (int a = 0; a < 4; ++a)
                #pragma unroll
                for (int o = 0; o < 4; ++o)
                    fma2(acc[a * 4 + o], fr2[a], wo2[o]);
        }
        __syncthreads();
    }

    float bias[4];
    #pragma unroll
    for (int o = 0; o < 4; ++o) bias[o] = Woutb[ox * 4 + o];
    #pragma unroll
    for (int a = 0; a < 4; ++a) {
        float4 v;
        float* vp = reinterpret_cast<float*>(&v);
        #pragma unroll
        for (int o = 0; o < 4; ++o) {
            float2 p = unpack2(acc[a * 4 + o]);
            float z = p.x + p.y + bias[o];
            vp[o] = 1.0f / (1.0f + __expf(-z));
        }
        int row = row0 + rx * 4 + a;
        *reinterpret_cast<float4*>(preds + (size_t)row * OUT_ + ox * 4) = v;
    }
}

// ============================================================================
extern "C" void kernel_launch(void* const* d_in, const int* in_sizes, int n_in,
                              void* d_out, int out_size) {
    (void)in_sizes; (void)n_in; (void)out_size;
    const float* inp   = (const float*)d_in[0];
    const float* fr0   = (const float*)d_in[1];
    const float* noise = (const float*)d_in[2];
    const float* Winw  = (const float*)d_in[3];
    const float* Winb  = (const float*)d_in[4];
    const float* Wrecw = (const float*)d_in[5];
    const float* Wrecb = (const float*)d_in[6];
    const float* Woutw = (const float*)d_in[7];
    const float* Woutb = (const float*)d_in[8];

    float* out   = (float*)d_out;
    float* preds = out;                                   // [B,T,OUT]
    float* rates = out + (size_t)B_ * T_ * OUT_;          // [B,T,H]

    k_prep_x<<<(T_ * KP_IN * B_) / 256, 256>>>(inp);
    k_prep_w<<<(KP_REC * H_) / 256, 256>>>(Wrecw, Winw);
    k_prep_misc<<<(H_ / 2 * B_) / 256, 256>>>(fr0, Woutw);
    k_rnn<<<NCTA, 256>>>(noise, Winb, Wrecb, fr0, rates);
    k_preds<<<(B_ * T_) / 64, 256>>>(fr0, Woutb, rates, preds);
}

// round 10
// speedup vs baseline: 1.9593x; 1.9593x over previous
#include <cuda_runtime.h>
#include <cuda_bf16.h>
#include <cstdint>
#include <cstddef>

#define B_    128
#define T_    512
#define IN_   64
#define H_    1024
#define OUT_  64

#define NCTA   128            // 4 b-groups x 32 h-groups

// ---- k_rnn smem layout (bytes) ----
#define WPITCH   2192         // 1088 bf16 + 16B pad  (548 words % 32 == 4: ldsm OK)
#define APITCH   272          // 128 bf16 + 16B pad   (68 words  % 32 == 4)
#define XPITCH   144          // 64 bf16 + 16B pad    (36 words  % 32 == 4)
#define OFF_W    0
#define W_STREAM 70144        // 32*WPITCH
#define OFF_A    140288       // 2 bufs x (hi+lo)
#define A_BUF    17408
#define A_STREAM 8704         // 32*APITCH
#define OFF_X    175104
#define X_STREAM 4608         // 32*XPITCH
#define OFF_D    184320       // 4 x [32][33] f32
#define D_KQ     4224
#define OFF_BIAS 201216
#define SMEM_TOT 201472

typedef unsigned long long u64;

// ---------------- static device scratch --------------------------------------
__device__ __nv_bfloat16 g_Ahi[B_][H_];        // fr hi (state, rewritten each step)
__device__ __nv_bfloat16 g_Alo[B_][H_];        // fr lo
__device__ __nv_bfloat16 g_Xhi[T_][B_][IN_];   // x hi (precomputed)
__device__ __nv_bfloat16 g_Xlo[T_][B_][IN_];
__device__ u64  g_WoutP[512 * OUT_];           // W_out pair-packed [kp][o]
__device__ unsigned g_arrive[4];               // per-b-group barrier
__device__ unsigned g_epoch[4];

// ---------------- helpers -----------------------------------------------------
static __device__ __forceinline__ uint32_t smem_u32(const void* p) {
    uint32_t a;
    asm("{ .reg .u64 t; cvta.to.shared.u64 t, %1; cvt.u32.u64 %0, t; }"
        : "=r"(a) : "l"(p));
    return a;
}
static __device__ __forceinline__ void ldsm4(uint32_t& r0, uint32_t& r1,
                                             uint32_t& r2, uint32_t& r3,
                                             uint32_t addr) {
    asm volatile("ldmatrix.sync.aligned.m8n8.x4.shared.b16 {%0,%1,%2,%3}, [%4];"
                 : "=r"(r0), "=r"(r1), "=r"(r2), "=r"(r3) : "r"(addr));
}
static __device__ __forceinline__ void ldsm2(uint32_t& r0, uint32_t& r1,
                                             uint32_t addr) {
    asm volatile("ldmatrix.sync.aligned.m8n8.x2.shared.b16 {%0,%1}, [%2];"
                 : "=r"(r0), "=r"(r1) : "r"(addr));
}
static __device__ __forceinline__ void mma16816(float* d, const uint32_t* a,
                                                uint32_t b0, uint32_t b1) {
    asm volatile(
        "mma.sync.aligned.m16n8k16.row.col.f32.bf16.bf16.f32 "
        "{%0,%1,%2,%3}, {%4,%5,%6,%7}, {%8,%9}, {%0,%1,%2,%3};"
        : "+f"(d[0]), "+f"(d[1]), "+f"(d[2]), "+f"(d[3])
        : "r"(a[0]), "r"(a[1]), "r"(a[2]), "r"(a[3]), "r"(b0), "r"(b1));
}
static __device__ __forceinline__ unsigned ld_acq(const unsigned* p) {
    unsigned v;
    asm volatile("ld.acquire.gpu.global.u32 %0, [%1];" : "=r"(v) : "l"(p));
    return v;
}
static __device__ __forceinline__ void st_rel(unsigned* p, unsigned v) {
    asm volatile("st.release.gpu.global.u32 [%0], %1;" :: "l"(p), "r"(v) : "memory");
}
// pack two floats to bf16x2 (memory order: x first, y second)
static __device__ __forceinline__ uint32_t bfpack(float x, float y) {
    uint32_t r;
    asm("cvt.rn.satfinite.bf16x2.f32 %0, %1, %2;" : "=r"(r) : "f"(y), "f"(x));
    return r;
}
static __device__ __forceinline__ u64 pack2(float x, float y) {
    u64 r; asm("mov.b64 %0, {%1,%2};" : "=l"(r) : "f"(x), "f"(y)); return r;
}
static __device__ __forceinline__ float2 unpack2(u64 v) {
    float2 r; asm("mov.b64 {%0,%1}, %2;" : "=f"(r.x), "=f"(r.y) : "l"(v)); return r;
}
static __device__ __forceinline__ void fma2(u64& acc, u64 a, u64 b) {
    asm("fma.rn.f32x2 %0, %1, %2, %0;" : "+l"(acc) : "l"(a), "l"(b));
}

// ============================================================================
// Prep: bf16 splits of x (all t) and fr0; W_out pack; barrier reset
// ============================================================================
__global__ void k_prep(const float* __restrict__ inp,
                       const float* __restrict__ fr0,
                       const float* __restrict__ Woutw) {
    int i = blockIdx.x * 256 + threadIdx.x;          // T*B*IN = 4,194,304
    {   // x split: i = t*8192 + b*64 + k
        int k = i & 63, b = (i >> 6) & 127, t = i >> 13;
        float f = inp[((size_t)b * T_ + t) * IN_ + k];
        __nv_bfloat16 hi = __float2bfloat16(f);
        __nv_bfloat16 lo = __float2bfloat16(f - __bfloat162float(hi));
        g_Xhi[t][b][k] = hi;
        g_Xlo[t][b][k] = lo;
    }
    if (i < B_ * H_) {                               // fr0 split
        int b = i >> 10, k = i & 1023;
        float f = fr0[(size_t)b * H_ + k];
        __nv_bfloat16 hi = __float2bfloat16(f);
        __nv_bfloat16 lo = __float2bfloat16(f - __bfloat162float(hi));
        g_Ahi[b][k] = hi;
        g_Alo[b][k] = lo;
    }
    if (i < 512 * OUT_) {                            // W_out^T pair pack
        int kp = i & 511, o = i >> 9;
        const float* s = Woutw + (size_t)o * H_ + 2 * kp;
        g_WoutP[(size_t)kp * OUT_ + o] = pack2(s[0], s[1]);
    }
    if (i < 4) { g_arrive[i] = 0u; g_epoch[i] = 0u; }
}

// ============================================================================
// Persistent HMMA RNN: 128 CTAs = (bg 0..3) x (hg 0..31), 256 threads.
// Warp = (mh 0..1, kq 0..3): m16 x n32 x k-slice, fp32 accumulators.
// ============================================================================
__global__ void __launch_bounds__(256, 1)
k_rnn(const float* __restrict__ noise,
      const float* __restrict__ Winw,  const float* __restrict__ Winb,
      const float* __restrict__ Wrecw, const float* __restrict__ Wrecb,
      const float* __restrict__ fr0,
      float* __restrict__ out_rates)
{
    extern __shared__ char smem[];
    const uint32_t sm = smem_u32(smem);
    const int tid  = threadIdx.x;
    const int wid  = tid >> 5;
    const int lane = tid & 31;
    const int bg   = blockIdx.x & 3;
    const int hg   = blockIdx.x >> 2;
    const int b0   = bg * 32;
    const int h0   = hg * 32;

    // ---- stage W slice (hi/lo bf16) once: rows = local h (n), cols = k ------
    for (int i = tid; i < 32 * 1088; i += 256) {
        int row = i / 1088, k = i - row * 1088;
        float w = (k < 1024) ? Wrecw[(size_t)(h0 + row) * H_ + k]
                             : Winw[(size_t)(h0 + row) * IN_ + (k - 1024)];
        __nv_bfloat16 hi = __float2bfloat16(w);
        __nv_bfloat16 lo = __float2bfloat16(w - __bfloat162float(hi));
        *reinterpret_cast<__nv_bfloat16*>(smem + OFF_W + row * WPITCH + k * 2) = hi;
        *reinterpret_cast<__nv_bfloat16*>(smem + OFF_W + W_STREAM + row * WPITCH + k * 2) = lo;
    }
    if (tid < 32)
        *reinterpret_cast<float*>(smem + OFF_BIAS + tid * 4) =
            Winb[h0 + tid] + Wrecb[h0 + tid];

    // ---- epilogue role: thread owns (b0+em, h0+en..+3); fr in registers -----
    const int em = tid >> 3;
    const int en = (tid & 7) * 4;
    const int eb = b0 + em;
    float frloc[4];
    {
        float4 f = *reinterpret_cast<const float4*>(fr0 + (size_t)eb * H_ + h0 + en);
        frloc[0] = f.x; frloc[1] = f.y; frloc[2] = f.z; frloc[3] = f.w;
    }
    __syncthreads();

    // ---- ldmatrix lane address components ------------------------------------
    const int mh = wid & 1;
    const int kq = wid >> 1;
    const int grp = lane >> 3, lr = lane & 7;
    const uint32_t aRow  = (uint32_t)(mh * 16 + (grp & 1) * 8 + lr);
    const uint32_t aCol2 = (uint32_t)((grp >> 1) * 8) * 2;        // bytes
    const uint32_t aOffA = aRow * APITCH + aCol2;                 // within A stream
    const uint32_t aOffX = aRow * XPITCH + aCol2;
    const uint32_t wOff  = (uint32_t)(lane & 7) * WPITCH + (uint32_t)(((lane >> 3) & 1) * 8) * 2;

    const unsigned barTgtStep = 32u;

    for (int t = 0; t < T_; ++t) {
        float acc[4][4];
        #pragma unroll
        for (int n = 0; n < 4; ++n)
            #pragma unroll
            for (int j = 0; j < 4; ++j) acc[n][j] = 0.0f;

        // ---- stage chunk 0 + x tile ------------------------------------------
        {
            #pragma unroll
            for (int it = 0; it < 4; ++it) {
                int u = tid + it * 256;
                int s = u >> 9, row = (u >> 4) & 31, q = u & 15;
                const __nv_bfloat16* src =
                    (s ? &g_Alo[b0 + row][q * 8] : &g_Ahi[b0 + row][q * 8]);
                uint4 v = __ldcg(reinterpret_cast<const uint4*>(src));
                *reinterpret_cast<uint4*>(
                    smem + OFF_A + s * A_STREAM + row * APITCH + q * 16) = v;
            }
            #pragma unroll
            for (int it = 0; it < 2; ++it) {
                int u = tid + it * 256;
                int s = u >> 8, row = (u >> 3) & 31, q = u & 7;
                const __nv_bfloat16* src =
                    (s ? &g_Xlo[t][b0 + row][q * 8] : &g_Xhi[t][b0 + row][q * 8]);
                uint4 v = __ldg(reinterpret_cast<const uint4*>(src));
                *reinterpret_cast<uint4*>(
                    smem + OFF_X + s * X_STREAM + row * XPITCH + q * 16) = v;
            }
        }
        __syncthreads();

        // ---- 8 fr chunks, double buffered --------------------------------------
        #pragma unroll 1
        for (int c = 0; c < 8; ++c) {
            if (c < 7) {                 // stage chunk c+1 into buf (c+1)&1
                int nb = (c + 1) & 1;
                #pragma unroll
                for (int it = 0; it < 4; ++it) {
                    int u = tid + it * 256;
                    int s = u >> 9, row = (u >> 4) & 31, q = u & 15;
                    const __nv_bfloat16* src =
                        (s ? &g_Alo[b0 + row][(c + 1) * 128 + q * 8]
                           : &g_Ahi[b0 + row][(c + 1) * 128 + q * 8]);
                    uint4 v = __ldcg(reinterpret_cast<const uint4*>(src));
                    *reinterpret_cast<uint4*>(
                        smem + OFF_A + nb * A_BUF + s * A_STREAM + row * APITCH + q * 16) = v;
                }
            }
            // MMA on chunk c from buf c&1
            {
                const uint32_t aHiB = sm + OFF_A + (c & 1) * A_BUF + aOffA;
                const uint32_t aLoB = aHiB + A_STREAM;
                #pragma unroll
                for (int s = 0; s < 2; ++s) {
                    const int klocal = kq * 32 + s * 16;
                    uint32_t ah[4], al[4];
                    ldsm4(ah[0], ah[1], ah[2], ah[3], aHiB + klocal * 2);
                    ldsm4(al[0], al[1], al[2], al[3], aLoB + klocal * 2);
                    const uint32_t wHiB = sm + OFF_W + wOff + (c * 128 + klocal) * 2;
                    #pragma unroll
                    for (int n = 0; n < 4; ++n) {
                        uint32_t wh0, wh1, wl0, wl1;
                        ldsm2(wh0, wh1, wHiB + n * (8 * WPITCH));
                        ldsm2(wl0, wl1, wHiB + W_STREAM + n * (8 * WPITCH));
                        mma16816(acc[n], ah, wh0, wh1);
                        mma16816(acc[n], al, wh0, wh1);
                        mma16816(acc[n], ah, wl0, wl1);
                    }
                }
            }
            __syncthreads();
        }

        // ---- x tile (K=64, one k-step per kq warp) -----------------------------
        {
            const int klocal = kq * 16;
            uint32_t ah[4], al[4];
            ldsm4(ah[0], ah[1], ah[2], ah[3], sm + OFF_X + aOffX + klocal * 2);
            ldsm4(al[0], al[1], al[2], al[3], sm + OFF_X + X_STREAM + aOffX + klocal * 2);
            const uint32_t wHiB = sm + OFF_W + wOff + (1024 + klocal) * 2;
            #pragma unroll
            for (int n = 0; n < 4; ++n) {
                uint32_t wh0, wh1, wl0, wl1;
                ldsm2(wh0, wh1, wHiB + n * (8 * WPITCH));
                ldsm2(wl0, wl1, wHiB + W_STREAM + n * (8 * WPITCH));
                mma16816(acc[n], ah, wh0, wh1);
                mma16816(acc[n], al, wh0, wh1);
                mma16816(acc[n], ah, wl0, wl1);
            }
        }

        // ---- write partial D to smem -------------------------------------------
        {
            float* dq = reinterpret_cast<float*>(smem + OFF_D + kq * D_KQ);
            const int rr = mh * 16 + (lane >> 2);
            const int cc = (lane & 3) * 2;
            #pragma unroll
            for (int n = 0; n < 4; ++n) {
                dq[rr * 33 + n * 8 + cc]           = acc[n][0];
                dq[rr * 33 + n * 8 + cc + 1]       = acc[n][1];
                dq[(rr + 8) * 33 + n * 8 + cc]     = acc[n][2];
                dq[(rr + 8) * 33 + n * 8 + cc + 1] = acc[n][3];
            }
        }
        __syncthreads();

        // ---- epilogue: kq reduce, bias+noise, tanh, leaky update ---------------
        {
            const float* dbase = reinterpret_cast<const float*>(smem + OFF_D);
            const float* bias  = reinterpret_cast<const float*>(smem + OFF_BIAS);
            float s[4] = {0.f, 0.f, 0.f, 0.f};
            #pragma unroll
            for (int q = 0; q < 4; ++q) {
                const float* src = dbase + q * (D_KQ / 4) + em * 33 + en;
                s[0] += src[0]; s[1] += src[1]; s[2] += src[2]; s[3] += src[3];
            }
            float4 nv = __ldg(reinterpret_cast<const float4*>(
                noise + ((size_t)t * B_ + eb) * H_ + h0 + en));
            float nn[4] = {nv.x, nv.y, nv.z, nv.w};
            #pragma unroll
            for (int j = 0; j < 4; ++j) {
                float pre = s[j] + bias[en + j] + nn[j];
                frloc[j] = 0.9f * frloc[j] + 0.1f * tanhf(pre);
            }
            // rates (fp32)
            *reinterpret_cast<float4*>(
                out_rates + ((size_t)eb * T_ + t) * H_ + h0 + en) =
                make_float4(frloc[0], frloc[1], frloc[2], frloc[3]);
            // bf16 hi/lo split -> global A
            float h0f = __bfloat162float(__float2bfloat16(frloc[0]));
            float h1f = __bfloat162float(__float2bfloat16(frloc[1]));
            float h2f = __bfloat162float(__float2bfloat16(frloc[2]));
            float h3f = __bfloat162float(__float2bfloat16(frloc[3]));
            uint2 whi = make_uint2(bfpack(frloc[0], frloc[1]),
                                   bfpack(frloc[2], frloc[3]));
            uint2 wlo = make_uint2(bfpack(frloc[0] - h0f, frloc[1] - h1f),
                                   bfpack(frloc[2] - h2f, frloc[3] - h3f));
            *reinterpret_cast<uint2*>(&g_Ahi[eb][h0 + en]) = whi;
            *reinterpret_cast<uint2*>(&g_Alo[eb][h0 + en]) = wlo;
        }

        // ---- per-b-group grid barrier (32 CTAs) --------------------------------
        if (t < T_ - 1) {
            __threadfence();
            __syncthreads();
            if (tid == 0) {
                unsigned old = atomicAdd(&g_arrive[bg], 1u);
                if (old == barTgtStep * (unsigned)(t + 1) - 1u)
                    st_rel(&g_epoch[bg], (unsigned)(t + 1));
                else
                    while (ld_acq(&g_epoch[bg]) < (unsigned)(t + 1)) {}
            }
            __syncthreads();
        }
    }
}

// ============================================================================
// preds: sigmoid(fr_{t-1} @ Wout^T + b) — unchanged tiled FFMA2 GEMM (R6)
// ============================================================================
#define PR_CH    32
#define PR_PITCH 66

__global__ void __launch_bounds__(256)
k_preds(const float* __restrict__ fr0,
        const float* __restrict__ Woutb,
        const float* __restrict__ rates,
        float* __restrict__ preds)
{
    __shared__ __align__(16) u64 sFr[PR_CH][PR_PITCH];
    __shared__ __align__(16) u64 sWo[PR_CH][PR_PITCH];

    const int tid  = threadIdx.x;
    const int rx   = tid >> 4;
    const int ox   = tid & 15;
    const int row0 = blockIdx.x * 64;

    u64 acc[16];
    #pragma unroll
    for (int j = 0; j < 16; ++j) acc[j] = 0ull;

    for (int c = 0; c < 512 / PR_CH; ++c) {
        #pragma unroll
        for (int it = 0; it < 4; ++it) {
            int i  = tid + it * 256;
            int f4 = i & 15, r = i >> 4;
            int row = row0 + r;
            int bb = row >> 9, tt = row & (T_ - 1);
            const float4* src = (tt == 0)
                ? reinterpret_cast<const float4*>(fr0 + (size_t)bb * H_)
                : reinterpret_cast<const float4*>(
                      rates + ((size_t)bb * T_ + (tt - 1)) * H_);
            float4 v = src[c * 16 + f4];
            sFr[f4 * 2][r]     = pack2(v.x, v.y);
            sFr[f4 * 2 + 1][r] = pack2(v.z, v.w);
        }
        #pragma unroll
        for (int it = 0; it < 4; ++it) {
            int i   = tid + it * 256;
            int u2  = i & 31, kpl = i >> 5;
            ulonglong2 v = *reinterpret_cast<const ulonglong2*>(
                &g_WoutP[(size_t)(c * PR_CH + kpl) * OUT_ + u2 * 2]);
            *reinterpret_cast<ulonglong2*>(&sWo[kpl][u2 * 2]) = v;
        }
        __syncthreads();

        #pragma unroll 4
        for (int kpl = 0; kpl < PR_CH; ++kpl) {
            ulonglong2 f01 = *reinterpret_cast<const ulonglong2*>(&sFr[kpl][rx * 4]);
            ulonglong2 f23 = *reinterpret_cast<const ulonglong2*>(&sFr[kpl][rx * 4 + 2]);
            ulonglong2 w01 = *reinterpret_cast<const ulonglong2*>(&sWo[kpl][ox * 4]);
            ulonglong2 w23 = *reinterpret_cast<const ulonglong2*>(&sWo[kpl][ox * 4 + 2]);
            u64 fr2[4] = {f01.x, f01.y, f23.x, f23.y};
            u64 wo2[4] = {w01.x, w01.y, w23.x, w23.y};
            #pragma unroll
            for (int a = 0; a < 4; ++a)
                #pragma unroll
                for (int o = 0; o < 4; ++o)
                    fma2(acc[a * 4 + o], fr2[a], wo2[o]);
        }
        __syncthreads();
    }

    float bias[4];
    #pragma unroll
    for (int o = 0; o < 4; ++o) bias[o] = Woutb[ox * 4 + o];
    #pragma unroll
    for (int a = 0; a < 4; ++a) {
        float4 v;
        float* vp = reinterpret_cast<float*>(&v);
        #pragma unroll
        for (int o = 0; o < 4; ++o) {
            float2 p = unpack2(acc[a * 4 + o]);
            float z = p.x + p.y + bias[o];
            vp[o] = 1.0f / (1.0f + __expf(-z));
        }
        int row = row0 + rx * 4 + a;
        *reinterpret_cast<float4*>(preds + (size_t)row * OUT_ + ox * 4) = v;
    }
}

// ============================================================================
extern "C" void kernel_launch(void* const* d_in, const int* in_sizes, int n_in,
                              void* d_out, int out_size) {
    (void)in_sizes; (void)n_in; (void)out_size;
    const float* inp   = (const float*)d_in[0];
    const float* fr0   = (const float*)d_in[1];
    const float* noise = (const float*)d_in[2];
    const float* Winw  = (const float*)d_in[3];
    const float* Winb  = (const float*)d_in[4];
    const float* Wrecw = (const float*)d_in[5];
    const float* Wrecb = (const float*)d_in[6];
    const float* Woutw = (const float*)d_in[7];
    const float* Woutb = (const float*)d_in[8];

    float* out   = (float*)d_out;
    float* preds = out;                                   // [B,T,OUT]
    float* rates = out + (size_t)B_ * T_ * OUT_;          // [B,T,H]

    static bool attr_set = false;
    if (!attr_set) {
        cudaFuncSetAttribute(k_rnn, cudaFuncAttributeMaxDynamicSharedMemorySize,
                             SMEM_TOT);
        attr_set = true;
    }

    k_prep<<<(T_ * B_ * IN_) / 256, 256>>>(inp, fr0, Woutw);
    k_rnn<<<NCTA, 256, SMEM_TOT>>>(noise, Winw, Winb, Wrecw, Wrecb, fr0, rates);
    k_preds<<<(B_ * T_) / 64, 256>>>(fr0, Woutb, rates, preds);
}

// round 11
// speedup vs baseline: 2.6834x; 1.3696x over previous
#include <cuda_runtime.h>
#include <cuda_bf16.h>
#include <cstdint>
#include <cstddef>

#define B_    128
#define T_    512
#define IN_   64
#define H_    1024
#define OUT_  64

#define NCTA   128            // 4 b-groups x 32 h-groups

// ---- k_rnn smem layout (bytes) ----
#define WPITCH   2192         // 1088 bf16 + 16B pad
#define APITCH   528          // 256 bf16 + 16B pad
#define XPITCH   144          // 64 bf16 + 16B pad
#define OFF_W    0
#define W_STREAM 70144        // 32*WPITCH
#define OFF_A    140288       // 2 bufs x (hi+lo streams)
#define A_STREAM 16896        // 32*APITCH
#define A_BUF    33792        // hi+lo
#define OFF_X    207872       // 2 streams x 32*XPITCH
#define X_STREAM 4608
#define OFF_D    OFF_A        // aliased onto A buf0 (free when D is written)
#define D_KQ     4224         // [32][33] f32
#define OFF_BIAS 217088
#define SMEM_TOT 217216

typedef unsigned long long u64;

// ---------------- static device scratch --------------------------------------
__device__ __nv_bfloat16 g_Ahi[B_][H_];        // fr hi (state, rewritten each step)
__device__ __nv_bfloat16 g_Alo[B_][H_];        // fr lo
__device__ __nv_bfloat16 g_Xhi[T_][B_][IN_];   // x hi (precomputed)
__device__ __nv_bfloat16 g_Xlo[T_][B_][IN_];
__device__ u64  g_WoutP[512 * OUT_];           // W_out pair-packed [kp][o]
__device__ unsigned g_arrive[4];               // per-b-group barrier
__device__ unsigned g_epoch[4];

// ---------------- helpers -----------------------------------------------------
static __device__ __forceinline__ uint32_t smem_u32(const void* p) {
    uint32_t a;
    asm("{ .reg .u64 t; cvta.to.shared.u64 t, %1; cvt.u32.u64 %0, t; }"
        : "=r"(a) : "l"(p));
    return a;
}
static __device__ __forceinline__ void ldsm4(uint32_t& r0, uint32_t& r1,
                                             uint32_t& r2, uint32_t& r3,
                                             uint32_t addr) {
    asm volatile("ldmatrix.sync.aligned.m8n8.x4.shared.b16 {%0,%1,%2,%3}, [%4];"
                 : "=r"(r0), "=r"(r1), "=r"(r2), "=r"(r3) : "r"(addr));
}
static __device__ __forceinline__ void ldsm2(uint32_t& r0, uint32_t& r1,
                                             uint32_t addr) {
    asm volatile("ldmatrix.sync.aligned.m8n8.x2.shared.b16 {%0,%1}, [%2];"
                 : "=r"(r0), "=r"(r1) : "r"(addr));
}
static __device__ __forceinline__ void mma16816(float* d, const uint32_t* a,
                                                uint32_t b0, uint32_t b1) {
    asm volatile(
        "mma.sync.aligned.m16n8k16.row.col.f32.bf16.bf16.f32 "
        "{%0,%1,%2,%3}, {%4,%5,%6,%7}, {%8,%9}, {%0,%1,%2,%3};"
        : "+f"(d[0]), "+f"(d[1]), "+f"(d[2]), "+f"(d[3])
        : "r"(a[0]), "r"(a[1]), "r"(a[2]), "r"(a[3]), "r"(b0), "r"(b1));
}
static __device__ __forceinline__ unsigned ld_acq(const unsigned* p) {
    unsigned v;
    asm volatile("ld.acquire.gpu.global.u32 %0, [%1];" : "=r"(v) : "l"(p));
    return v;
}
static __device__ __forceinline__ void st_rel(unsigned* p, unsigned v) {
    asm volatile("st.release.gpu.global.u32 [%0], %1;" :: "l"(p), "r"(v) : "memory");
}
static __device__ __forceinline__ unsigned atom_add_rel(unsigned* p, unsigned v) {
    unsigned old;
    asm volatile("atom.add.release.gpu.global.u32 %0, [%1], %2;"
                 : "=r"(old) : "l"(p), "r"(v) : "memory");
    return old;
}
// pack two floats to bf16x2 (memory order: x first, y second)
static __device__ __forceinline__ uint32_t bfpack(float x, float y) {
    uint32_t r;
    asm("cvt.rn.satfinite.bf16x2.f32 %0, %1, %2;" : "=r"(r) : "f"(y), "f"(x));
    return r;
}
static __device__ __forceinline__ u64 pack2(float x, float y) {
    u64 r; asm("mov.b64 %0, {%1,%2};" : "=l"(r) : "f"(x), "f"(y)); return r;
}
static __device__ __forceinline__ float2 unpack2(u64 v) {
    float2 r; asm("mov.b64 {%0,%1}, %2;" : "=f"(r.x), "=f"(r.y) : "l"(v)); return r;
}
static __device__ __forceinline__ void fma2(u64& acc, u64 a, u64 b) {
    asm("fma.rn.f32x2 %0, %1, %2, %0;" : "+l"(acc) : "l"(a), "l"(b));
}

// ============================================================================
// Prep: bf16 splits of x (all t) and fr0; W_out pack; barrier reset
// ============================================================================
__global__ void k_prep(const float* __restrict__ inp,
                       const float* __restrict__ fr0,
                       const float* __restrict__ Woutw) {
    int i = blockIdx.x * 256 + threadIdx.x;          // T*B*IN = 4,194,304
    {   // x split: i = t*8192 + b*64 + k
        int k = i & 63, b = (i >> 6) & 127, t = i >> 13;
        float f = inp[((size_t)b * T_ + t) * IN_ + k];
        __nv_bfloat16 hi = __float2bfloat16(f);
        __nv_bfloat16 lo = __float2bfloat16(f - __bfloat162float(hi));
        g_Xhi[t][b][k] = hi;
        g_Xlo[t][b][k] = lo;
    }
    if (i < B_ * H_) {                               // fr0 split
        int b = i >> 10, k = i & 1023;
        float f = fr0[(size_t)b * H_ + k];
        __nv_bfloat16 hi = __float2bfloat16(f);
        __nv_bfloat16 lo = __float2bfloat16(f - __bfloat162float(hi));
        g_Ahi[b][k] = hi;
        g_Alo[b][k] = lo;
    }
    if (i < 512 * OUT_) {                            // W_out^T pair pack
        int kp = i & 511, o = i >> 9;
        const float* s = Woutw + (size_t)o * H_ + 2 * kp;
        g_WoutP[(size_t)kp * OUT_ + o] = pack2(s[0], s[1]);
    }
    if (i < 4) { g_arrive[i] = 0u; g_epoch[i] = 0u; }
}

// ============================================================================
// Persistent HMMA RNN: 128 CTAs = (bg 0..3) x (hg 0..31), 256 threads.
// Warp = (mh 0..1, kq 0..3). 4 fr chunks of 256k, reg-prefetch double buffer.
// ============================================================================
__global__ void __launch_bounds__(256, 1)
k_rnn(const float* __restrict__ noise,
      const float* __restrict__ Winw,  const float* __restrict__ Winb,
      const float* __restrict__ Wrecw, const float* __restrict__ Wrecb,
      const float* __restrict__ fr0,
      float* __restrict__ out_rates)
{
    extern __shared__ char smem[];
    const uint32_t sm = smem_u32(smem);
    const int tid  = threadIdx.x;
    const int wid  = tid >> 5;
    const int lane = tid & 31;
    const int bg   = blockIdx.x & 3;
    const int hg   = blockIdx.x >> 2;
    const int b0   = bg * 32;
    const int h0   = hg * 32;

    // ---- stage W slice (hi/lo bf16) once: rows = local h (n), cols = k ------
    for (int i = tid; i < 32 * 1088; i += 256) {
        int row = i / 1088, k = i - row * 1088;
        float w = (k < 1024) ? Wrecw[(size_t)(h0 + row) * H_ + k]
                             : Winw[(size_t)(h0 + row) * IN_ + (k - 1024)];
        __nv_bfloat16 hi = __float2bfloat16(w);
        __nv_bfloat16 lo = __float2bfloat16(w - __bfloat162float(hi));
        *reinterpret_cast<__nv_bfloat16*>(smem + OFF_W + row * WPITCH + k * 2) = hi;
        *reinterpret_cast<__nv_bfloat16*>(smem + OFF_W + W_STREAM + row * WPITCH + k * 2) = lo;
    }
    if (tid < 32)
        *reinterpret_cast<float*>(smem + OFF_BIAS + tid * 4) =
            Winb[h0 + tid] + Wrecb[h0 + tid];

    // ---- epilogue role: thread owns (b0+em, h0+en..+3); fr in registers -----
    const int em = tid >> 3;
    const int en = (tid & 7) * 4;
    const int eb = b0 + em;
    float frloc[4];
    {
        float4 f = *reinterpret_cast<const float4*>(fr0 + (size_t)eb * H_ + h0 + en);
        frloc[0] = f.x; frloc[1] = f.y; frloc[2] = f.z; frloc[3] = f.w;
    }
    __syncthreads();

    // ---- ldmatrix lane address components ------------------------------------
    const int mh = wid & 1;
    const int kq = wid >> 1;
    const int grp = lane >> 3, lr = lane & 7;
    const uint32_t aRow  = (uint32_t)(mh * 16 + (grp & 1) * 8 + lr);
    const uint32_t aCol2 = (uint32_t)((grp >> 1) * 8) * 2;
    const uint32_t aOffA = aRow * APITCH + aCol2;
    const uint32_t aOffX = aRow * XPITCH + aCol2;
    const uint32_t wOff  = (uint32_t)(lane & 7) * WPITCH + (uint32_t)(((lane >> 3) & 1) * 8) * 2;

    // staging maps (per thread): chunk = 2048 uint4; X = 512 uint4
    int pfS[8], pfRow[8], pfQ[8];
    #pragma unroll
    for (int it = 0; it < 8; ++it) {
        int u = tid + it * 256;
        pfS[it] = u >> 10; pfRow[it] = (u >> 5) & 31; pfQ[it] = u & 31;
    }

    for (int t = 0; t < T_; ++t) {
        // ---- prefetch noise (consumed in epilogue) ---------------------------
        float4 nv = __ldg(reinterpret_cast<const float4*>(
            noise + ((size_t)t * B_ + eb) * H_ + h0 + en));

        // ---- stage X (hi/lo) --------------------------------------------------
        #pragma unroll
        for (int it = 0; it < 2; ++it) {
            int u = tid + it * 256;
            int s = u >> 8, row = (u >> 3) & 31, q = u & 7;
            const __nv_bfloat16* src =
                (s ? &g_Xlo[t][b0 + row][q * 8] : &g_Xhi[t][b0 + row][q * 8]);
            uint4 v = __ldg(reinterpret_cast<const uint4*>(src));
            *reinterpret_cast<uint4*>(
                smem + OFF_X + s * X_STREAM + row * XPITCH + q * 16) = v;
        }
        // ---- prefetch chunk 0 into registers ----------------------------------
        uint4 pf[8];
        #pragma unroll
        for (int it = 0; it < 8; ++it) {
            const __nv_bfloat16* src =
                (pfS[it] ? &g_Alo[b0 + pfRow[it]][pfQ[it] * 8]
                         : &g_Ahi[b0 + pfRow[it]][pfQ[it] * 8]);
            pf[it] = __ldcg(reinterpret_cast<const uint4*>(src));
        }
        __syncthreads();   // X visible

        float acc[4][4];
        #pragma unroll
        for (int n = 0; n < 4; ++n)
            #pragma unroll
            for (int j = 0; j < 4; ++j) acc[n][j] = 0.0f;

        // ---- x-tile MMA first (overlaps chunk0 LDG latency) --------------------
        {
            const int klocal = kq * 16;
            uint32_t ah[4], al[4];
            ldsm4(ah[0], ah[1], ah[2], ah[3], sm + OFF_X + aOffX + klocal * 2);
            ldsm4(al[0], al[1], al[2], al[3], sm + OFF_X + X_STREAM + aOffX + klocal * 2);
            const uint32_t wHiB = sm + OFF_W + wOff + (1024 + klocal) * 2;
            #pragma unroll
            for (int n = 0; n < 4; ++n) {
                uint32_t wh0, wh1, wl0, wl1;
                ldsm2(wh0, wh1, wHiB + n * (8 * WPITCH));
                ldsm2(wl0, wl1, wHiB + W_STREAM + n * (8 * WPITCH));
                mma16816(acc[n], ah, wh0, wh1);
                mma16816(acc[n], al, wh0, wh1);
                mma16816(acc[n], ah, wl0, wl1);
            }
        }
        // ---- store chunk0; prefetch chunk1 -------------------------------------
        #pragma unroll
        for (int it = 0; it < 8; ++it)
            *reinterpret_cast<uint4*>(smem + OFF_A + pfS[it] * A_STREAM +
                                      pfRow[it] * APITCH + pfQ[it] * 16) = pf[it];
        #pragma unroll
        for (int it = 0; it < 8; ++it) {
            const __nv_bfloat16* src =
                (pfS[it] ? &g_Alo[b0 + pfRow[it]][256 + pfQ[it] * 8]
                         : &g_Ahi[b0 + pfRow[it]][256 + pfQ[it] * 8]);
            pf[it] = __ldcg(reinterpret_cast<const uint4*>(src));
        }
        __syncthreads();   // buf0 visible

        // ---- 4 chunks of 256k, double buffered ---------------------------------
        #pragma unroll
        for (int c = 0; c < 4; ++c) {
            {
                const uint32_t aHiB = sm + OFF_A + (c & 1) * A_BUF + aOffA;
                const uint32_t aLoB = aHiB + A_STREAM;
                #pragma unroll
                for (int s = 0; s < 4; ++s) {
                    const int klocal = kq * 64 + s * 16;
                    uint32_t ah[4], al[4];
                    ldsm4(ah[0], ah[1], ah[2], ah[3], aHiB + klocal * 2);
                    ldsm4(al[0], al[1], al[2], al[3], aLoB + klocal * 2);
                    const uint32_t wHiB = sm + OFF_W + wOff + (c * 256 + klocal) * 2;
                    #pragma unroll
                    for (int n = 0; n < 4; ++n) {
                        uint32_t wh0, wh1, wl0, wl1;
                        ldsm2(wh0, wh1, wHiB + n * (8 * WPITCH));
                        ldsm2(wl0, wl1, wHiB + W_STREAM + n * (8 * WPITCH));
                        mma16816(acc[n], ah, wh0, wh1);
                        mma16816(acc[n], al, wh0, wh1);
                        mma16816(acc[n], ah, wl0, wl1);
                    }
                }
            }
            if (c < 3) {
                const int nb = (c + 1) & 1;
                #pragma unroll
                for (int it = 0; it < 8; ++it)
                    *reinterpret_cast<uint4*>(smem + OFF_A + nb * A_BUF +
                                              pfS[it] * A_STREAM +
                                              pfRow[it] * APITCH + pfQ[it] * 16) = pf[it];
                if (c < 2) {
                    #pragma unroll
                    for (int it = 0; it < 8; ++it) {
                        const __nv_bfloat16* src =
                            (pfS[it] ? &g_Alo[b0 + pfRow[it]][(c + 2) * 256 + pfQ[it] * 8]
                                     : &g_Ahi[b0 + pfRow[it]][(c + 2) * 256 + pfQ[it] * 8]);
                        pf[it] = __ldcg(reinterpret_cast<const uint4*>(src));
                    }
                }
                __syncthreads();
            }
        }

        // ---- write partial D (aliased on A buf0; chunk3 reads buf1) ------------
        {
            float* dq = reinterpret_cast<float*>(smem + OFF_D + kq * D_KQ);
            const int rr = mh * 16 + (lane >> 2);
            const int cc = (lane & 3) * 2;
            #pragma unroll
            for (int n = 0; n < 4; ++n) {
                dq[rr * 33 + n * 8 + cc]           = acc[n][0];
                dq[rr * 33 + n * 8 + cc + 1]       = acc[n][1];
                dq[(rr + 8) * 33 + n * 8 + cc]     = acc[n][2];
                dq[(rr + 8) * 33 + n * 8 + cc + 1] = acc[n][3];
            }
        }
        __syncthreads();

        // ---- epilogue: kq reduce, bias+noise, tanh, leaky update ---------------
        {
            const float* dbase = reinterpret_cast<const float*>(smem + OFF_D);
            const float* bias  = reinterpret_cast<const float*>(smem + OFF_BIAS);
            float s[4] = {0.f, 0.f, 0.f, 0.f};
            #pragma unroll
            for (int q = 0; q < 4; ++q) {
                const float* src = dbase + q * (D_KQ / 4) + em * 33 + en;
                s[0] += src[0]; s[1] += src[1]; s[2] += src[2]; s[3] += src[3];
            }
            float nn[4] = {nv.x, nv.y, nv.z, nv.w};
            #pragma unroll
            for (int j = 0; j < 4; ++j) {
                float pre = s[j] + bias[en + j] + nn[j];
                frloc[j] = 0.9f * frloc[j] + 0.1f * tanhf(pre);
            }
            *reinterpret_cast<float4*>(
                out_rates + ((size_t)eb * T_ + t) * H_ + h0 + en) =
                make_float4(frloc[0], frloc[1], frloc[2], frloc[3]);
            float h0f = __bfloat162float(__float2bfloat16(frloc[0]));
            float h1f = __bfloat162float(__float2bfloat16(frloc[1]));
            float h2f = __bfloat162float(__float2bfloat16(frloc[2]));
            float h3f = __bfloat162float(__float2bfloat16(frloc[3]));
            uint2 whi = make_uint2(bfpack(frloc[0], frloc[1]),
                                   bfpack(frloc[2], frloc[3]));
            uint2 wlo = make_uint2(bfpack(frloc[0] - h0f, frloc[1] - h1f),
                                   bfpack(frloc[2] - h2f, frloc[3] - h3f));
            *reinterpret_cast<uint2*>(&g_Ahi[eb][h0 + en]) = whi;
            *reinterpret_cast<uint2*>(&g_Alo[eb][h0 + en]) = wlo;
        }

        // ---- per-b-group grid barrier: release-atomic arrive -------------------
        if (t < T_ - 1) {
            __syncthreads();   // all CTA's fr writes done before release
            if (tid == 0) {
                unsigned old = atom_add_rel(&g_arrive[bg], 1u);
                if (old == 32u * (unsigned)(t + 1) - 1u)
                    st_rel(&g_epoch[bg], (unsigned)(t + 1));
                else
                    while (ld_acq(&g_epoch[bg]) < (unsigned)(t + 1)) {}
            }
            __syncthreads();
        }
    }
}

// ============================================================================
// preds: sigmoid(fr_{t-1} @ Wout^T + b) — unchanged tiled FFMA2 GEMM (R6)
// ============================================================================
#define PR_CH    32
#define PR_PITCH 66

__global__ void __launch_bounds__(256)
k_preds(const float* __restrict__ fr0,
        const float* __restrict__ Woutb,
        const float* __restrict__ rates,
        float* __restrict__ preds)
{
    __shared__ __align__(16) u64 sFr[PR_CH][PR_PITCH];
    __shared__ __align__(16) u64 sWo[PR_CH][PR_PITCH];

    const int tid  = threadIdx.x;
    const int rx   = tid >> 4;
    const int ox   = tid & 15;
    const int row0 = blockIdx.x * 64;

    u64 acc[16];
    #pragma unroll
    for (int j = 0; j < 16; ++j) acc[j] = 0ull;

    for (int c = 0; c < 512 / PR_CH; ++c) {
        #pragma unroll
        for (int it = 0; it < 4; ++it) {
            int i  = tid + it * 256;
            int f4 = i & 15, r = i >> 4;
            int row = row0 + r;
            int bb = row >> 9, tt = row & (T_ - 1);
            const float4* src = (tt == 0)
                ? reinterpret_cast<const float4*>(fr0 + (size_t)bb * H_)
                : reinterpret_cast<const float4*>(
                      rates + ((size_t)bb * T_ + (tt - 1)) * H_);
            float4 v = src[c * 16 + f4];
            sFr[f4 * 2][r]     = pack2(v.x, v.y);
            sFr[f4 * 2 + 1][r] = pack2(v.z, v.w);
        }
        #pragma unroll
        for (int it = 0; it < 4; ++it) {
            int i   = tid + it * 256;
            int u2  = i & 31, kpl = i >> 5;
            ulonglong2 v = *reinterpret_cast<const ulonglong2*>(
                &g_WoutP[(size_t)(c * PR_CH + kpl) * OUT_ + u2 * 2]);
            *reinterpret_cast<ulonglong2*>(&sWo[kpl][u2 * 2]) = v;
        }
        __syncthreads();

        #pragma unroll 4
        for (int kpl = 0; kpl < PR_CH; ++kpl) {
            ulonglong2 f01 = *reinterpret_cast<const ulonglong2*>(&sFr[kpl][rx * 4]);
            ulonglong2 f23 = *reinterpret_cast<const ulonglong2*>(&sFr[kpl][rx * 4 + 2]);
            ulonglong2 w01 = *reinterpret_cast<const ulonglong2*>(&sWo[kpl][ox * 4]);
            ulonglong2 w23 = *reinterpret_cast<const ulonglong2*>(&sWo[kpl][ox * 4 + 2]);
            u64 fr2[4] = {f01.x, f01.y, f23.x, f23.y};
            u64 wo2[4] = {w01.x, w01.y, w23.x, w23.y};
            #pragma unroll
            for (int a = 0; a < 4; ++a)
                #pragma unroll
                for (int o = 0; o < 4; ++o)
                    fma2(acc[a * 4 + o], fr2[a], wo2[o]);
        }
        __syncthreads();
    }

    float bias[4];
    #pragma unroll
    for (int o = 0; o < 4; ++o) bias[o] = Woutb[ox * 4 + o];
    #pragma unroll
    for (int a = 0; a < 4; ++a) {
        float4 v;
        float* vp = reinterpret_cast<float*>(&v);
        #pragma unroll
        for (int o = 0; o < 4; ++o) {
            float2 p = unpack2(acc[a * 4 + o]);
            float z = p.x + p.y + bias[o];
            vp[o] = 1.0f / (1.0f + __expf(-z));
        }
        int row = row0 + rx * 4 + a;
        *reinterpret_cast<float4*>(preds + (size_t)row * OUT_ + ox * 4) = v;
    }
}

// ============================================================================
extern "C" void kernel_launch(void* const* d_in, const int* in_sizes, int n_in,
                              void* d_out, int out_size) {
    (void)in_sizes; (void)n_in; (void)out_size;
    const float* inp   = (const float*)d_in[0];
    const float* fr0   = (const float*)d_in[1];
    const float* noise = (const float*)d_in[2];
    const float* Winw  = (const float*)d_in[3];
    const float* Winb  = (const float*)d_in[4];
    const float* Wrecw = (const float*)d_in[5];
    const float* Wrecb = (const float*)d_in[6];
    const float* Woutw = (const float*)d_in[7];
    const float* Woutb = (const float*)d_in[8];

    float* out   = (float*)d_out;
    float* preds = out;                                   // [B,T,OUT]
    float* rates = out + (size_t)B_ * T_ * OUT_;          // [B,T,H]

    static bool attr_set = false;
    if (!attr_set) {
        cudaFuncSetAttribute(k_rnn, cudaFuncAttributeMaxDynamicSharedMemorySize,
                             SMEM_TOT);
        attr_set = true;
    }

    k_prep<<<(T_ * B_ * IN_) / 256, 256>>>(inp, fr0, Woutw);
    k_rnn<<<NCTA, 256, SMEM_TOT>>>(noise, Winw, Winb, Wrecw, Wrecb, fr0, rates);
    k_preds<<<(B_ * T_) / 64, 256>>>(fr0, Woutb, rates, preds);
}